// round 3
// baseline (speedup 1.0000x reference)
#include <cuda_runtime.h>
#include <cuda_bf16.h>
#include <cstdint>
#include <math.h>

// ---------------- problem constants ----------------
#define KB_   8
#define KT_   4096
#define KD_   768
#define KH_   12
#define KHD_  64
#define KINT_ 3
#define KBT_  (KB_ * KT_)                 // 32768
#define KNELEM_ ((size_t)KBT_ * KD_)      // 25165824
#define KSPLIT_ 2304                      // 3 * 768 (hi | lo | hi concat along K)
#define WELEM_ (KD_ * KD_)

// GEMM tiling
#define BM_ 128
#define BN_ 128
#define BK_ 64
#define KITERS_ (KSPLIT_ / BK_)           // 36
#define STAGES_ 4
#define STAGE_BYTES_ 32768u               // A 16KB + B 16KB
#define OFF_B_ 16384u
#define SMEM_BYTES_ (STAGES_ * STAGE_BYTES_)   // 131072

// ---------------- device scratch ----------------
__device__ __nv_bfloat16 g_a2[(size_t)KBT_ * KSPLIT_];       // split activations (x, then attn out)
__device__ __nv_bfloat16 g_w2[4 * (size_t)KD_ * KSPLIT_];    // split transposed weights
__device__ float g_q[KNELEM_];
__device__ float g_k[KNELEM_];
__device__ float g_v[KNELEM_];
__device__ float g_o[KNELEM_];

// ---------------- helpers ----------------
__device__ __forceinline__ uint32_t smem_u32(const void* p) {
    return (uint32_t)__cvta_generic_to_shared(p);
}

__device__ __forceinline__ void cp_async16(uint32_t saddr, const void* gaddr) {
    asm volatile("cp.async.cg.shared.global [%0], [%1], 16;" :: "r"(saddr), "l"(gaddr));
}
#define CP_COMMIT_()  asm volatile("cp.async.commit_group;" ::: "memory")
#define CP_WAIT_(n)   asm volatile("cp.async.wait_group %0;" :: "n"(n) : "memory")

__device__ __forceinline__ void ldsm_x4(uint32_t& r0, uint32_t& r1, uint32_t& r2, uint32_t& r3,
                                        uint32_t addr) {
    asm volatile("ldmatrix.sync.aligned.m8n8.x4.shared.b16 {%0,%1,%2,%3}, [%4];"
                 : "=r"(r0), "=r"(r1), "=r"(r2), "=r"(r3) : "r"(addr));
}

__device__ __forceinline__ void mma_bf16(float* c, const uint32_t* a, const uint32_t* b) {
    asm volatile(
        "mma.sync.aligned.m16n8k16.row.col.f32.bf16.bf16.f32 "
        "{%0,%1,%2,%3}, {%4,%5,%6,%7}, {%8,%9}, {%0,%1,%2,%3};"
        : "+f"(c[0]), "+f"(c[1]), "+f"(c[2]), "+f"(c[3])
        : "r"(a[0]), "r"(a[1]), "r"(a[2]), "r"(a[3]), "r"(b[0]), "r"(b[1]));
}

// ---------------- kernel 1: transpose + split weights ----------------
// W'[n][k] blocks: [0:768)=hi, [768:1536)=hi, [1536:2304)=lo ; paired with A blocks hi|lo|hi
__global__ __launch_bounds__(256) void prep_weights_kernel(
    const float* __restrict__ Wq, const float* __restrict__ Wk,
    const float* __restrict__ Wv, const float* __restrict__ Wo) {
    int idx = blockIdx.x * 256 + threadIdx.x;       // over D*D
    int n = idx / KD_;
    int k = idx - n * KD_;
    const float* Ws[4] = {Wq, Wk, Wv, Wo};
#pragma unroll
    for (int w = 0; w < 4; w++) {
        float val = Ws[w][(size_t)k * KD_ + n];     // W[k][n] -> B[n][k]
        __nv_bfloat16 hi = __float2bfloat16(val);
        __nv_bfloat16 lo = __float2bfloat16(val - __bfloat162float(hi));
        size_t base = (size_t)w * KD_ * KSPLIT_ + (size_t)n * KSPLIT_;
        g_w2[base + k]        = hi;
        g_w2[base + 768 + k]  = hi;
        g_w2[base + 1536 + k] = lo;
    }
}

// ---------------- kernel 2: split x -> [hi | lo | hi] rows of 2304 ----------------
__global__ __launch_bounds__(256) void split_x_kernel(const float* __restrict__ x) {
    int gid = blockIdx.x * 256 + threadIdx.x;       // over KNELEM/2
    long long i = (long long)gid * 2;
    int row = (int)(i / KD_);
    int col = (int)(i - (long long)row * KD_);
    float a = x[i], b = x[i + 1];
    __nv_bfloat16 ah = __float2bfloat16(a), bh = __float2bfloat16(b);
    __nv_bfloat16 al = __float2bfloat16(a - __bfloat162float(ah));
    __nv_bfloat16 bl = __float2bfloat16(b - __bfloat162float(bh));
    __nv_bfloat162 hh = __halves2bfloat162(ah, bh);
    __nv_bfloat162 ll = __halves2bfloat162(al, bl);
    size_t base = (size_t)row * KSPLIT_ + col;
    *reinterpret_cast<__nv_bfloat162*>(&g_a2[base])        = hh;
    *reinterpret_cast<__nv_bfloat162*>(&g_a2[base + 768])  = ll;
    *reinterpret_cast<__nv_bfloat162*>(&g_a2[base + 1536]) = hh;
}

// ---------------- kernel 3: pipelined bf16 mma.sync GEMM ----------------
// C[32768,768] = A'[32768,2304] * B'[768,2304]^T + bias
__global__ __launch_bounds__(256, 1) void gemm_kernel(
    const __nv_bfloat16* __restrict__ A, const __nv_bfloat16* __restrict__ B,
    const float* __restrict__ bias, float* __restrict__ C) {
    extern __shared__ char smem[];
    const uint32_t sb = smem_u32(smem);
    const int tid = threadIdx.x, lane = tid & 31, wid = tid >> 5;
    const int m0 = blockIdx.y * BM_;
    const int n0 = blockIdx.x * BN_;
    const int wm = (wid >> 2) * 64;     // 2 m-warps x 64
    const int wn = (wid & 3) * 32;      // 4 n-warps x 32

    // loader constants: 1024 16B-chunks per tile; thread covers rows tid>>3 + 32*it
    const int arow = tid >> 3, acg = tid & 7;
    const __nv_bfloat16* Abase = A + (size_t)m0 * KSPLIT_;
    const __nv_bfloat16* Bbase = B + (size_t)n0 * KSPLIT_;

    // ldmatrix lane constants
    const int a_row_l = wm + (lane & 15);
    const uint32_t a_xor = (uint32_t)(a_row_l & 7) << 4;
    const uint32_t a_k2 = (uint32_t)(lane >> 4) * 16;
    const int gq = lane >> 3;
    const int b_row_l = wn + (gq >> 1) * 8 + (lane & 7);
    const uint32_t b_xor = (uint32_t)(b_row_l & 7) << 4;
    const uint32_t b_k2 = (uint32_t)(gq & 1) * 16;

    float acc[4][4][4];
#pragma unroll
    for (int i = 0; i < 4; i++)
#pragma unroll
        for (int j = 0; j < 4; j++)
#pragma unroll
            for (int r = 0; r < 4; r++) acc[i][j][r] = 0.f;

#define LOAD_STAGE_(s, kc)                                                          \
    {                                                                               \
        uint32_t st_ = sb + (uint32_t)(s) * STAGE_BYTES_;                           \
        int k0_ = (kc) * BK_;                                                       \
        _Pragma("unroll")                                                           \
        for (int it_ = 0; it_ < 4; it_++) {                                         \
            int row_ = arow + it_ * 32;                                             \
            uint32_t so_ = st_ + (uint32_t)row_ * 128 +                             \
                           (((uint32_t)acg * 16) ^ ((uint32_t)(row_ & 7) << 4));    \
            cp_async16(so_, Abase + (size_t)row_ * KSPLIT_ + k0_ + acg * 8);        \
            cp_async16(so_ + OFF_B_, Bbase + (size_t)row_ * KSPLIT_ + k0_ + acg * 8);\
        }                                                                           \
    }

    // prologue: stages 0..2
    LOAD_STAGE_(0, 0); CP_COMMIT_();
    LOAD_STAGE_(1, 1); CP_COMMIT_();
    LOAD_STAGE_(2, 2); CP_COMMIT_();

    uint32_t Af[2][4][4], Bf[2][4][2];

#define LOAD_FRAGS_(st, ks, buf)                                                    \
    {                                                                               \
        _Pragma("unroll")                                                           \
        for (int mf_ = 0; mf_ < 4; mf_++) {                                         \
            uint32_t ad_ = (st) + (uint32_t)(a_row_l + mf_ * 16) * 128 +            \
                           (((uint32_t)((ks) * 32) + a_k2) ^ a_xor);                \
            ldsm_x4(Af[buf][mf_][0], Af[buf][mf_][1], Af[buf][mf_][2],              \
                    Af[buf][mf_][3], ad_);                                          \
        }                                                                           \
        _Pragma("unroll")                                                           \
        for (int np_ = 0; np_ < 2; np_++) {                                         \
            uint32_t bd_ = (st) + OFF_B_ + (uint32_t)(b_row_l + np_ * 16) * 128 +   \
                           (((uint32_t)((ks) * 32) + b_k2) ^ b_xor);                \
            uint32_t r0_, r1_, r2_, r3_;                                            \
            ldsm_x4(r0_, r1_, r2_, r3_, bd_);                                       \
            Bf[buf][np_ * 2][0] = r0_; Bf[buf][np_ * 2][1] = r1_;                   \
            Bf[buf][np_ * 2 + 1][0] = r2_; Bf[buf][np_ * 2 + 1][1] = r3_;           \
        }                                                                           \
    }

    for (int kc = 0; kc < KITERS_; kc++) {
        CP_WAIT_(2);
        __syncthreads();
        if (kc + 3 < KITERS_) { LOAD_STAGE_((kc + 3) & 3, kc + 3); }
        CP_COMMIT_();
        uint32_t st = sb + (uint32_t)(kc & 3) * STAGE_BYTES_;
        LOAD_FRAGS_(st, 0, 0);
#pragma unroll
        for (int ks = 0; ks < 4; ks++) {
            if (ks < 3) LOAD_FRAGS_(st, ks + 1, (ks + 1) & 1);
#pragma unroll
            for (int mf = 0; mf < 4; mf++)
#pragma unroll
                for (int nf = 0; nf < 4; nf++)
                    mma_bf16(acc[mf][nf], Af[ks & 1][mf], Bf[ks & 1][nf]);
        }
    }

    // epilogue: direct fp32 stores + bias
    const int crow0 = m0 + wm + (lane >> 2);
    const int ccol0 = n0 + wn + (lane & 3) * 2;
#pragma unroll
    for (int mf = 0; mf < 4; mf++) {
#pragma unroll
        for (int nf = 0; nf < 4; nf++) {
            int col = ccol0 + nf * 8;
            float b0 = bias[col], b1 = bias[col + 1];
            int r0 = crow0 + mf * 16;
            float2 v0 = make_float2(acc[mf][nf][0] + b0, acc[mf][nf][1] + b1);
            float2 v1 = make_float2(acc[mf][nf][2] + b0, acc[mf][nf][3] + b1);
            *reinterpret_cast<float2*>(C + (size_t)r0 * KD_ + col) = v0;
            *reinterpret_cast<float2*>(C + (size_t)(r0 + 8) * KD_ + col) = v1;
        }
    }
#undef LOAD_STAGE_
#undef LOAD_FRAGS_
}

// ---------------- kernel 4: 3-tap local attention (warp per token-head) ----------------
__global__ __launch_bounds__(256) void local_attn_kernel() {
    int gw = (blockIdx.x * 256 + threadIdx.x) >> 5;      // KBT_*KH_ warps
    int lid = threadIdx.x & 31;
    int token = gw / KH_;
    int h = gw - token * KH_;
    int t = token & (KT_ - 1);
    size_t base = (size_t)token * KD_ + h * KHD_;
    int d0 = lid * 2;

    float q0 = g_q[base + d0];
    float q1 = g_q[base + d0 + 1];

    float sc[3];
#pragma unroll
    for (int j = 0; j < 3; j++) {
        int off = (j - 1) * KINT_;
        bool valid = ((unsigned)(t + off) < (unsigned)KT_);
        float p = 0.f;
        if (valid) {
            size_t kb = (size_t)((long long)base + (long long)off * KD_);
            p = q0 * g_k[kb + d0] + q1 * g_k[kb + d0 + 1];
        }
#pragma unroll
        for (int m = 16; m; m >>= 1) p += __shfl_xor_sync(0xffffffffu, p, m);
        sc[j] = valid ? p * 0.125f : -INFINITY;          // 1/sqrt(64)
    }
    float mx = fmaxf(sc[0], fmaxf(sc[1], sc[2]));
    float e[3], den = 0.f;
#pragma unroll
    for (int j = 0; j < 3; j++) { e[j] = expf(sc[j] - mx); den += e[j]; }
    float rden = 1.f / den;

    float a0 = 0.f, a1 = 0.f;
#pragma unroll
    for (int j = 0; j < 3; j++) {
        int off = (j - 1) * KINT_;
        if ((unsigned)(t + off) < (unsigned)KT_) {
            size_t vb = (size_t)((long long)base + (long long)off * KD_);
            float w = e[j] * rden;
            a0 += w * g_v[vb + d0];
            a1 += w * g_v[vb + d0 + 1];
        }
    }
    __nv_bfloat16 h0 = __float2bfloat16(a0);
    __nv_bfloat16 h1 = __float2bfloat16(a1);
    __nv_bfloat16 l0 = __float2bfloat16(a0 - __bfloat162float(h0));
    __nv_bfloat16 l1 = __float2bfloat16(a1 - __bfloat162float(h1));
    __nv_bfloat162 hh = __halves2bfloat162(h0, h1);
    __nv_bfloat162 ll = __halves2bfloat162(l0, l1);
    size_t base2 = (size_t)token * KSPLIT_ + h * KHD_ + d0;
    *reinterpret_cast<__nv_bfloat162*>(&g_a2[base2])        = hh;
    *reinterpret_cast<__nv_bfloat162*>(&g_a2[base2 + 768])  = ll;
    *reinterpret_cast<__nv_bfloat162*>(&g_a2[base2 + 1536]) = hh;
}

// ---------------- kernel 5: residual + LayerNorm ----------------
__global__ __launch_bounds__(256) void ln_kernel(
    const float* __restrict__ x, const float* __restrict__ gamma,
    const float* __restrict__ beta, float* __restrict__ out) {
    __shared__ float s_sum[8], s_sq[8];
    int r = blockIdx.x, tid = threadIdx.x, wid = tid >> 5, lid = tid & 31;
    size_t base = (size_t)r * KD_;

    float y[3], s = 0.f, s2 = 0.f;
#pragma unroll
    for (int i = 0; i < 3; i++) {
        int c = tid + i * 256;
        float v = g_o[base + c] + x[base + c];
        y[i] = v; s += v; s2 += v * v;
    }
#pragma unroll
    for (int m = 16; m; m >>= 1) {
        s  += __shfl_xor_sync(0xffffffffu, s, m);
        s2 += __shfl_xor_sync(0xffffffffu, s2, m);
    }
    if (lid == 0) { s_sum[wid] = s; s_sq[wid] = s2; }
    __syncthreads();
    float ts = 0.f, ts2 = 0.f;
#pragma unroll
    for (int i = 0; i < 8; i++) { ts += s_sum[i]; ts2 += s_sq[i]; }
    float mean = ts * (1.f / KD_);
    float var  = ts2 * (1.f / KD_) - mean * mean;
    float inv  = rsqrtf(var + 1e-5f);
#pragma unroll
    for (int i = 0; i < 3; i++) {
        int c = tid + i * 256;
        out[base + c] = (y[i] - mean) * inv * gamma[c] + beta[c];
    }
}

// ---------------- launch ----------------
extern "C" void kernel_launch(void* const* d_in, const int* in_sizes, int n_in,
                              void* d_out, int out_size) {
    const float* x     = (const float*)d_in[0];
    const float* Wq    = (const float*)d_in[1];
    const float* bq    = (const float*)d_in[2];
    const float* Wk    = (const float*)d_in[3];
    const float* bk    = (const float*)d_in[4];
    const float* Wv    = (const float*)d_in[5];
    const float* bv    = (const float*)d_in[6];
    const float* Wo    = (const float*)d_in[7];
    const float* bo    = (const float*)d_in[8];
    const float* gamma = (const float*)d_in[9];
    const float* beta  = (const float*)d_in[10];

    void *p_a2, *p_w2, *p_q, *p_k, *p_v, *p_o;
    cudaGetSymbolAddress(&p_a2, g_a2);
    cudaGetSymbolAddress(&p_w2, g_w2);
    cudaGetSymbolAddress(&p_q,  g_q);
    cudaGetSymbolAddress(&p_k,  g_k);
    cudaGetSymbolAddress(&p_v,  g_v);
    cudaGetSymbolAddress(&p_o,  g_o);

    const __nv_bfloat16* a2 = (const __nv_bfloat16*)p_a2;
    const __nv_bfloat16* w2 = (const __nv_bfloat16*)p_w2;
    const size_t WSTRIDE = (size_t)KD_ * KSPLIT_;

    cudaFuncSetAttribute(gemm_kernel,
                         cudaFuncAttributeMaxDynamicSharedMemorySize, (int)SMEM_BYTES_);

    prep_weights_kernel<<<WELEM_ / 256, 256>>>(Wq, Wk, Wv, Wo);
    split_x_kernel<<<(int)(KNELEM_ / 2 / 256), 256>>>(x);

    dim3 ggrid(KD_ / BN_, KBT_ / BM_);   // (6, 256): n fastest for A-tile L2 reuse
    gemm_kernel<<<ggrid, 256, SMEM_BYTES_>>>(a2, w2 + 0 * WSTRIDE, bq, (float*)p_q);
    gemm_kernel<<<ggrid, 256, SMEM_BYTES_>>>(a2, w2 + 1 * WSTRIDE, bk, (float*)p_k);
    gemm_kernel<<<ggrid, 256, SMEM_BYTES_>>>(a2, w2 + 2 * WSTRIDE, bv, (float*)p_v);
    local_attn_kernel<<<KBT_ * KH_ / 8, 256>>>();
    gemm_kernel<<<ggrid, 256, SMEM_BYTES_>>>(a2, w2 + 3 * WSTRIDE, bo, (float*)p_o);
    ln_kernel<<<KBT_, 256>>>(x, gamma, beta, (float*)d_out);
}

// round 5
// speedup vs baseline: 1.1125x; 1.1125x over previous
#include <cuda_runtime.h>
#include <cuda_bf16.h>
#include <cstdint>
#include <math.h>

// ---------------- problem constants ----------------
#define KB_   8
#define KT_   4096
#define KD_   768
#define KH_   12
#define KHD_  64
#define KINT_ 3
#define KBT_  (KB_ * KT_)                 // 32768
#define KNELEM_ ((size_t)KBT_ * KD_)      // 25165824
#define KSPLIT_ 2304                      // 3 * 768 (hi | lo | hi concat along K)
#define KNQKV_ 2304                       // Wq|Wk|Wv stacked along N
#define WELEM_ (KD_ * KD_)

// GEMM tiling
#define BM_ 128
#define BN_ 256
#define BK_ 64
#define KITERS_ (KSPLIT_ / BK_)           // 36
#define STAGES_ 4
#define STAGE_BYTES_ 49152u               // A 16KB + B 32KB
#define OFF_B_ 16384u
#define SMEM_BYTES_ (STAGES_ * STAGE_BYTES_)   // 196608

// ---------------- device scratch ----------------
__device__ __nv_bfloat16 g_a2[(size_t)KBT_ * KSPLIT_];       // split activations
__device__ __nv_bfloat16 g_w2[4 * (size_t)KD_ * KSPLIT_];    // split transposed weights (q,k,v,o)
__device__ float g_bqkv[KNQKV_];                             // concat bias q|k|v
__device__ float g_qkv[(size_t)KBT_ * KNQKV_];               // fused QKV output
__device__ float g_o[KNELEM_];

// ---------------- helpers ----------------
__device__ __forceinline__ uint32_t smem_u32(const void* p) {
    return (uint32_t)__cvta_generic_to_shared(p);
}

__device__ __forceinline__ void cp_async16(uint32_t saddr, const void* gaddr) {
    asm volatile("cp.async.cg.shared.global [%0], [%1], 16;" :: "r"(saddr), "l"(gaddr));
}
#define CP_COMMIT_()  asm volatile("cp.async.commit_group;" ::: "memory")
#define CP_WAIT_(n)   asm volatile("cp.async.wait_group %0;" :: "n"(n) : "memory")

__device__ __forceinline__ void ldsm_x4(uint32_t& r0, uint32_t& r1, uint32_t& r2, uint32_t& r3,
                                        uint32_t addr) {
    asm volatile("ldmatrix.sync.aligned.m8n8.x4.shared.b16 {%0,%1,%2,%3}, [%4];"
                 : "=r"(r0), "=r"(r1), "=r"(r2), "=r"(r3) : "r"(addr));
}

__device__ __forceinline__ void mma_bf16(float* c, const uint32_t* a, const uint32_t* b) {
    asm volatile(
        "mma.sync.aligned.m16n8k16.row.col.f32.bf16.bf16.f32 "
        "{%0,%1,%2,%3}, {%4,%5,%6,%7}, {%8,%9}, {%0,%1,%2,%3};"
        : "+f"(c[0]), "+f"(c[1]), "+f"(c[2]), "+f"(c[3])
        : "r"(a[0]), "r"(a[1]), "r"(a[2]), "r"(a[3]), "r"(b[0]), "r"(b[1]));
}

// ---------------- kernel 1: transpose + split weights, concat bias ----------------
// W'[n][k'] blocks: [0:768)=hi, [768:1536)=hi, [1536:2304)=lo ; pairs with A = hi|lo|hi
__global__ __launch_bounds__(256) void prep_weights_kernel(
    const float* __restrict__ Wq, const float* __restrict__ Wk,
    const float* __restrict__ Wv, const float* __restrict__ Wo,
    const float* __restrict__ bq, const float* __restrict__ bk,
    const float* __restrict__ bv) {
    int idx = blockIdx.x * 256 + threadIdx.x;       // over D*D
    int n = idx / KD_;
    int k = idx - n * KD_;
    const float* Ws[4] = {Wq, Wk, Wv, Wo};
#pragma unroll
    for (int w = 0; w < 4; w++) {
        float val = Ws[w][(size_t)k * KD_ + n];     // W[k][n] -> B[n][k]
        __nv_bfloat16 hi = __float2bfloat16(val);
        __nv_bfloat16 lo = __float2bfloat16(val - __bfloat162float(hi));
        size_t base = (size_t)w * KD_ * KSPLIT_ + (size_t)n * KSPLIT_;
        g_w2[base + k]        = hi;
        g_w2[base + 768 + k]  = hi;
        g_w2[base + 1536 + k] = lo;
    }
    if (idx < KNQKV_) {
        g_bqkv[idx] = (idx < 768) ? bq[idx] : (idx < 1536) ? bk[idx - 768] : bv[idx - 1536];
    }
}

// ---------------- kernel 2: split x -> [hi | lo | hi] rows of 2304 ----------------
__global__ __launch_bounds__(256) void split_x_kernel(const float* __restrict__ x) {
    int gid = blockIdx.x * 256 + threadIdx.x;       // over KNELEM/2
    long long i = (long long)gid * 2;
    int row = (int)(i / KD_);
    int col = (int)(i - (long long)row * KD_);
    float a = x[i], b = x[i + 1];
    __nv_bfloat16 ah = __float2bfloat16(a), bh = __float2bfloat16(b);
    __nv_bfloat16 al = __float2bfloat16(a - __bfloat162float(ah));
    __nv_bfloat16 bl = __float2bfloat16(b - __bfloat162float(bh));
    __nv_bfloat162 hh = __halves2bfloat162(ah, bh);
    __nv_bfloat162 ll = __halves2bfloat162(al, bl);
    size_t base = (size_t)row * KSPLIT_ + col;
    *reinterpret_cast<__nv_bfloat162*>(&g_a2[base])        = hh;
    *reinterpret_cast<__nv_bfloat162*>(&g_a2[base + 768])  = ll;
    *reinterpret_cast<__nv_bfloat162*>(&g_a2[base + 1536]) = hh;
}

// ---------------- kernel 3: pipelined bf16 mma.sync GEMM (128x256 CTA, 64x64 warp) ----------------
// C[M, ldc] = A'[M,2304] * B'[ldc,2304]^T + bias
__global__ __launch_bounds__(256, 1) void gemm_kernel(
    const __nv_bfloat16* __restrict__ A, const __nv_bfloat16* __restrict__ B,
    const float* __restrict__ bias, float* __restrict__ C, int ldc) {
    extern __shared__ char smem[];
    const uint32_t sb = smem_u32(smem);
    const int tid = threadIdx.x, lane = tid & 31, wid = tid >> 5;
    const int m0 = blockIdx.y * BM_;
    const int n0 = blockIdx.x * BN_;
    const int wm = (wid >> 2) * 64;     // 2 m-warps x 64
    const int wn = (wid & 3) * 64;      // 4 n-warps x 64

    const int arow = tid >> 3, acg = tid & 7;
    const __nv_bfloat16* Abase = A + (size_t)m0 * KSPLIT_;
    const __nv_bfloat16* Bbase = B + (size_t)n0 * KSPLIT_;

    // ldmatrix lane constants
    const int a_row_l = wm + (lane & 15);
    const uint32_t a_xor = (uint32_t)(a_row_l & 7) << 4;
    const uint32_t a_k2 = (uint32_t)(lane >> 4) * 16;
    const int gq = lane >> 3;
    const int b_row_l = wn + (gq >> 1) * 8 + (lane & 7);
    const uint32_t b_xor = (uint32_t)(b_row_l & 7) << 4;
    const uint32_t b_k2 = (uint32_t)(gq & 1) * 16;

    float acc[4][8][4];
#pragma unroll
    for (int i = 0; i < 4; i++)
#pragma unroll
        for (int j = 0; j < 8; j++)
#pragma unroll
            for (int r = 0; r < 4; r++) acc[i][j][r] = 0.f;

#define LOAD_STAGE_(s, kc)                                                          \
    {                                                                               \
        uint32_t st_ = sb + (uint32_t)(s) * STAGE_BYTES_;                           \
        int k0_ = (kc) * BK_;                                                       \
        _Pragma("unroll")                                                           \
        for (int it_ = 0; it_ < 4; it_++) {                                         \
            int row_ = arow + it_ * 32;                                             \
            uint32_t so_ = st_ + (uint32_t)row_ * 128 +                             \
                           (((uint32_t)acg * 16) ^ ((uint32_t)(row_ & 7) << 4));    \
            cp_async16(so_, Abase + (size_t)row_ * KSPLIT_ + k0_ + acg * 8);        \
        }                                                                           \
        _Pragma("unroll")                                                           \
        for (int it_ = 0; it_ < 8; it_++) {                                         \
            int row_ = arow + it_ * 32;                                             \
            uint32_t so_ = st_ + OFF_B_ + (uint32_t)row_ * 128 +                    \
                           (((uint32_t)acg * 16) ^ ((uint32_t)(row_ & 7) << 4));    \
            cp_async16(so_, Bbase + (size_t)row_ * KSPLIT_ + k0_ + acg * 8);        \
        }                                                                           \
    }

    LOAD_STAGE_(0, 0); CP_COMMIT_();
    LOAD_STAGE_(1, 1); CP_COMMIT_();
    LOAD_STAGE_(2, 2); CP_COMMIT_();

    uint32_t Af[2][4][4], Bf[2][8][2];

#define LOAD_FRAGS_(st, ks, buf)                                                    \
    {                                                                               \
        _Pragma("unroll")                                                           \
        for (int mf_ = 0; mf_ < 4; mf_++) {                                         \
            uint32_t ad_ = (st) + (uint32_t)(a_row_l + mf_ * 16) * 128 +            \
                           (((uint32_t)((ks) * 32) + a_k2) ^ a_xor);                \
            ldsm_x4(Af[buf][mf_][0], Af[buf][mf_][1], Af[buf][mf_][2],              \
                    Af[buf][mf_][3], ad_);                                          \
        }                                                                           \
        _Pragma("unroll")                                                           \
        for (int np_ = 0; np_ < 4; np_++) {                                         \
            uint32_t bd_ = (st) + OFF_B_ + (uint32_t)(b_row_l + np_ * 16) * 128 +   \
                           (((uint32_t)((ks) * 32) + b_k2) ^ b_xor);                \
            uint32_t r0_, r1_, r2_, r3_;                                            \
            ldsm_x4(r0_, r1_, r2_, r3_, bd_);                                       \
            Bf[buf][np_ * 2][0] = r0_; Bf[buf][np_ * 2][1] = r1_;                   \
            Bf[buf][np_ * 2 + 1][0] = r2_; Bf[buf][np_ * 2 + 1][1] = r3_;           \
        }                                                                           \
    }

    for (int kc = 0; kc < KITERS_; kc++) {
        CP_WAIT_(2);
        __syncthreads();
        if (kc + 3 < KITERS_) { LOAD_STAGE_((kc + 3) & 3, kc + 3); }
        CP_COMMIT_();
        uint32_t st = sb + (uint32_t)(kc & 3) * STAGE_BYTES_;
        LOAD_FRAGS_(st, 0, 0);
#pragma unroll
        for (int ks = 0; ks < 4; ks++) {
            if (ks < 3) LOAD_FRAGS_(st, ks + 1, (ks + 1) & 1);
#pragma unroll
            for (int mf = 0; mf < 4; mf++)
#pragma unroll
                for (int nf = 0; nf < 8; nf++)
                    mma_bf16(acc[mf][nf], Af[ks & 1][mf], Bf[ks & 1][nf]);
        }
    }

    // epilogue: fp32 stores + bias
    const int crow0 = m0 + wm + (lane >> 2);
    const int ccol0 = n0 + wn + (lane & 3) * 2;
#pragma unroll
    for (int mf = 0; mf < 4; mf++) {
#pragma unroll
        for (int nf = 0; nf < 8; nf++) {
            int col = ccol0 + nf * 8;
            float b0 = bias[col], b1 = bias[col + 1];
            int r0 = crow0 + mf * 16;
            float2 v0 = make_float2(acc[mf][nf][0] + b0, acc[mf][nf][1] + b1);
            float2 v1 = make_float2(acc[mf][nf][2] + b0, acc[mf][nf][3] + b1);
            *reinterpret_cast<float2*>(C + (size_t)r0 * ldc + col) = v0;
            *reinterpret_cast<float2*>(C + (size_t)(r0 + 8) * ldc + col) = v1;
        }
    }
#undef LOAD_STAGE_
#undef LOAD_FRAGS_
}

// ---------------- kernel 4: 3-tap local attention (warp per token-head) ----------------
__global__ __launch_bounds__(256) void local_attn_kernel() {
    int gw = (blockIdx.x * 256 + threadIdx.x) >> 5;      // KBT_*KH_ warps
    int lid = threadIdx.x & 31;
    int token = gw / KH_;
    int h = gw - token * KH_;
    int t = token & (KT_ - 1);
    size_t base = (size_t)token * KNQKV_ + h * KHD_;     // q at +0, k at +768, v at +1536
    int d0 = lid * 2;

    float q0 = g_qkv[base + d0];
    float q1 = g_qkv[base + d0 + 1];

    float sc[3];
#pragma unroll
    for (int j = 0; j < 3; j++) {
        int off = (j - 1) * KINT_;
        bool valid = ((unsigned)(t + off) < (unsigned)KT_);
        float p = 0.f;
        if (valid) {
            size_t kb = (size_t)((long long)base + (long long)off * KNQKV_) + 768;
            p = q0 * g_qkv[kb + d0] + q1 * g_qkv[kb + d0 + 1];
        }
#pragma unroll
        for (int m = 16; m; m >>= 1) p += __shfl_xor_sync(0xffffffffu, p, m);
        sc[j] = valid ? p * 0.125f : -INFINITY;          // 1/sqrt(64)
    }
    float mx = fmaxf(sc[0], fmaxf(sc[1], sc[2]));
    float e[3], den = 0.f;
#pragma unroll
    for (int j = 0; j < 3; j++) { e[j] = expf(sc[j] - mx); den += e[j]; }
    float rden = 1.f / den;

    float a0 = 0.f, a1 = 0.f;
#pragma unroll
    for (int j = 0; j < 3; j++) {
        int off = (j - 1) * KINT_;
        if ((unsigned)(t + off) < (unsigned)KT_) {
            size_t vb = (size_t)((long long)base + (long long)off * KNQKV_) + 1536;
            float w = e[j] * rden;
            a0 += w * g_qkv[vb + d0];
            a1 += w * g_qkv[vb + d0 + 1];
        }
    }
    __nv_bfloat16 h0 = __float2bfloat16(a0);
    __nv_bfloat16 h1 = __float2bfloat16(a1);
    __nv_bfloat16 l0 = __float2bfloat16(a0 - __bfloat162float(h0));
    __nv_bfloat16 l1 = __float2bfloat16(a1 - __bfloat162float(h1));
    __nv_bfloat162 hh = __halves2bfloat162(h0, h1);
    __nv_bfloat162 ll = __halves2bfloat162(l0, l1);
    size_t base2 = (size_t)token * KSPLIT_ + h * KHD_ + d0;
    *reinterpret_cast<__nv_bfloat162*>(&g_a2[base2])        = hh;
    *reinterpret_cast<__nv_bfloat162*>(&g_a2[base2 + 768])  = ll;
    *reinterpret_cast<__nv_bfloat162*>(&g_a2[base2 + 1536]) = hh;
}

// ---------------- kernel 5: residual + LayerNorm ----------------
__global__ __launch_bounds__(256) void ln_kernel(
    const float* __restrict__ x, const float* __restrict__ gamma,
    const float* __restrict__ beta, float* __restrict__ out) {
    __shared__ float s_sum[8], s_sq[8];
    int r = blockIdx.x, tid = threadIdx.x, wid = tid >> 5, lid = tid & 31;
    size_t base = (size_t)r * KD_;

    float y[3], s = 0.f, s2 = 0.f;
#pragma unroll
    for (int i = 0; i < 3; i++) {
        int c = tid + i * 256;
        float v = g_o[base + c] + x[base + c];
        y[i] = v; s += v; s2 += v * v;
    }
#pragma unroll
    for (int m = 16; m; m >>= 1) {
        s  += __shfl_xor_sync(0xffffffffu, s, m);
        s2 += __shfl_xor_sync(0xffffffffu, s2, m);
    }
    if (lid == 0) { s_sum[wid] = s; s_sq[wid] = s2; }
    __syncthreads();
    float ts = 0.f, ts2 = 0.f;
#pragma unroll
    for (int i = 0; i < 8; i++) { ts += s_sum[i]; ts2 += s_sq[i]; }
    float mean = ts * (1.f / KD_);
    float var  = ts2 * (1.f / KD_) - mean * mean;
    float inv  = rsqrtf(var + 1e-5f);
#pragma unroll
    for (int i = 0; i < 3; i++) {
        int c = tid + i * 256;
        out[base + c] = (y[i] - mean) * inv * gamma[c] + beta[c];
    }
}

// ---------------- launch ----------------
extern "C" void kernel_launch(void* const* d_in, const int* in_sizes, int n_in,
                              void* d_out, int out_size) {
    const float* x     = (const float*)d_in[0];
    const float* Wq    = (const float*)d_in[1];
    const float* bq    = (const float*)d_in[2];
    const float* Wk    = (const float*)d_in[3];
    const float* bk    = (const float*)d_in[4];
    const float* Wv    = (const float*)d_in[5];
    const float* bv    = (const float*)d_in[6];
    const float* Wo    = (const float*)d_in[7];
    const float* bo    = (const float*)d_in[8];
    const float* gamma = (const float*)d_in[9];
    const float* beta  = (const float*)d_in[10];

    void *p_a2, *p_w2, *p_qkv, *p_o, *p_bqkv;
    cudaGetSymbolAddress(&p_a2,  g_a2);
    cudaGetSymbolAddress(&p_w2,  g_w2);
    cudaGetSymbolAddress(&p_qkv, g_qkv);
    cudaGetSymbolAddress(&p_o,   g_o);
    cudaGetSymbolAddress(&p_bqkv, g_bqkv);

    const __nv_bfloat16* a2 = (const __nv_bfloat16*)p_a2;
    const __nv_bfloat16* w2 = (const __nv_bfloat16*)p_w2;
    const size_t WSTRIDE = (size_t)KD_ * KSPLIT_;

    cudaFuncSetAttribute(gemm_kernel,
                         cudaFuncAttributeMaxDynamicSharedMemorySize, (int)SMEM_BYTES_);

    prep_weights_kernel<<<WELEM_ / 256, 256>>>(Wq, Wk, Wv, Wo, bq, bk, bv);
    split_x_kernel<<<(int)(KNELEM_ / 2 / 256), 256>>>(x);

    // fused QKV: C[32768, 2304]
    dim3 gqkv(KNQKV_ / BN_, KBT_ / BM_);   // (9, 256)
    gemm_kernel<<<gqkv, 256, SMEM_BYTES_>>>(a2, w2, (const float*)p_bqkv,
                                            (float*)p_qkv, KNQKV_);
    local_attn_kernel<<<KBT_ * KH_ / 8, 256>>>();
    // O projection: C[32768, 768]
    dim3 go(KD_ / BN_, KBT_ / BM_);        // (3, 256)
    gemm_kernel<<<go, 256, SMEM_BYTES_>>>(a2, w2 + 3 * WSTRIDE, bo, (float*)p_o, KD_);
    ln_kernel<<<KBT_, 256>>>(x, gamma, beta, (float*)d_out);
}

// round 7
// speedup vs baseline: 1.1775x; 1.0585x over previous
#include <cuda_runtime.h>
#include <cuda_bf16.h>
#include <cstdint>
#include <math.h>

// ---------------- problem constants ----------------
#define KB_   8
#define KT_   4096
#define KD_   768
#define KH_   12
#define KHD_  64
#define KINT_ 3
#define KBT_  (KB_ * KT_)                 // 32768
#define KNELEM_ ((size_t)KBT_ * KD_)      // 25165824
#define KSPLIT_ 2304                      // 3 * 768 (hi | lo | hi concat along K)
#define KNQKV_ 2304                       // Wq|Wk|Wv stacked along N
#define WELEM_ (KD_ * KD_)

// GEMM tiling
#define BM_ 128
#define BN_ 256
#define BK_ 64
#define KITERS_ (KSPLIT_ / BK_)           // 36
#define STAGES_ 4
#define STAGE_BYTES_ 49152u               // A 16KB + B 32KB
#define OFF_B_ 16384u
#define SMEM_BYTES_ (STAGES_ * STAGE_BYTES_)   // 196608

// ---------------- device scratch ----------------
__device__ __nv_bfloat16 g_a2[(size_t)KBT_ * KSPLIT_];       // split activations
__device__ __nv_bfloat16 g_w2[4 * (size_t)KD_ * KSPLIT_];    // split transposed weights (q,k,v,o)
__device__ float g_bqkv[KNQKV_];                             // concat bias q|k|v
__device__ float g_qkv[(size_t)KBT_ * KNQKV_];               // fused QKV output
__device__ float g_o[KNELEM_];

// ---------------- helpers ----------------
__device__ __forceinline__ uint32_t smem_u32(const void* p) {
    return (uint32_t)__cvta_generic_to_shared(p);
}

__device__ __forceinline__ void cp_async16(uint32_t saddr, const void* gaddr) {
    asm volatile("cp.async.cg.shared.global [%0], [%1], 16;" :: "r"(saddr), "l"(gaddr));
}
#define CP_COMMIT_()  asm volatile("cp.async.commit_group;" ::: "memory")
#define CP_WAIT_(n)   asm volatile("cp.async.wait_group %0;" :: "n"(n) : "memory")

__device__ __forceinline__ void ldsm_x4(uint32_t& r0, uint32_t& r1, uint32_t& r2, uint32_t& r3,
                                        uint32_t addr) {
    asm volatile("ldmatrix.sync.aligned.m8n8.x4.shared.b16 {%0,%1,%2,%3}, [%4];"
                 : "=r"(r0), "=r"(r1), "=r"(r2), "=r"(r3) : "r"(addr));
}

__device__ __forceinline__ void mma_bf16(float* c, const uint32_t* a, const uint32_t* b) {
    asm volatile(
        "mma.sync.aligned.m16n8k16.row.col.f32.bf16.bf16.f32 "
        "{%0,%1,%2,%3}, {%4,%5,%6,%7}, {%8,%9}, {%0,%1,%2,%3};"
        : "+f"(c[0]), "+f"(c[1]), "+f"(c[2]), "+f"(c[3])
        : "r"(a[0]), "r"(a[1]), "r"(a[2]), "r"(a[3]), "r"(b[0]), "r"(b[1]));
}

// ---------------- kernel 1: transpose + split weights, concat bias ----------------
__global__ __launch_bounds__(256) void prep_weights_kernel(
    const float* __restrict__ Wq, const float* __restrict__ Wk,
    const float* __restrict__ Wv, const float* __restrict__ Wo,
    const float* __restrict__ bq, const float* __restrict__ bk,
    const float* __restrict__ bv) {
    int idx = blockIdx.x * 256 + threadIdx.x;       // over D*D
    int n = idx / KD_;
    int k = idx - n * KD_;
    const float* Ws[4] = {Wq, Wk, Wv, Wo};
#pragma unroll
    for (int w = 0; w < 4; w++) {
        float val = Ws[w][(size_t)k * KD_ + n];     // W[k][n] -> B[n][k]
        __nv_bfloat16 hi = __float2bfloat16(val);
        __nv_bfloat16 lo = __float2bfloat16(val - __bfloat162float(hi));
        size_t base = (size_t)w * KD_ * KSPLIT_ + (size_t)n * KSPLIT_;
        g_w2[base + k]        = hi;
        g_w2[base + 768 + k]  = hi;
        g_w2[base + 1536 + k] = lo;
    }
    if (idx < KNQKV_) {
        g_bqkv[idx] = (idx < 768) ? bq[idx] : (idx < 1536) ? bk[idx - 768] : bv[idx - 1536];
    }
}

// ---------------- kernel 2: split x -> [hi | lo | hi] rows of 2304 (float4) ----------------
__global__ __launch_bounds__(256) void split_x_kernel(const float* __restrict__ x) {
    long long gid = (long long)blockIdx.x * 256 + threadIdx.x;   // over KNELEM/4
    long long i = gid * 4;
    int row = (int)(i / KD_);
    int col = (int)(i - (long long)row * KD_);
    float4 v = *reinterpret_cast<const float4*>(x + i);
    __nv_bfloat16 h0 = __float2bfloat16(v.x), h1 = __float2bfloat16(v.y);
    __nv_bfloat16 h2 = __float2bfloat16(v.z), h3 = __float2bfloat16(v.w);
    __nv_bfloat16 l0 = __float2bfloat16(v.x - __bfloat162float(h0));
    __nv_bfloat16 l1 = __float2bfloat16(v.y - __bfloat162float(h1));
    __nv_bfloat16 l2 = __float2bfloat16(v.z - __bfloat162float(h2));
    __nv_bfloat16 l3 = __float2bfloat16(v.w - __bfloat162float(h3));
    uint2 hh, ll;
    hh.x = ((uint32_t)__bfloat16_as_ushort(h1) << 16) | __bfloat16_as_ushort(h0);
    hh.y = ((uint32_t)__bfloat16_as_ushort(h3) << 16) | __bfloat16_as_ushort(h2);
    ll.x = ((uint32_t)__bfloat16_as_ushort(l1) << 16) | __bfloat16_as_ushort(l0);
    ll.y = ((uint32_t)__bfloat16_as_ushort(l3) << 16) | __bfloat16_as_ushort(l2);
    size_t base = (size_t)row * KSPLIT_ + col;
    *reinterpret_cast<uint2*>(&g_a2[base])        = hh;
    *reinterpret_cast<uint2*>(&g_a2[base + 768])  = ll;
    *reinterpret_cast<uint2*>(&g_a2[base + 1536]) = hh;
}

// ---------------- kernel 3: pipelined bf16 mma.sync GEMM (128x256 CTA, 64x64 warp) ----------------
// C[M, ldc] = A'[M,2304] * B'[ldc,2304]^T + bias
__global__ __launch_bounds__(256, 1) void gemm_kernel(
    const __nv_bfloat16* __restrict__ A, const __nv_bfloat16* __restrict__ B,
    const float* __restrict__ bias, float* __restrict__ C, int ldc) {
    extern __shared__ char smem[];
    const uint32_t sb = smem_u32(smem);
    const int tid = threadIdx.x, lane = tid & 31, wid = tid >> 5;
    const int m0 = blockIdx.y * BM_;
    const int n0 = blockIdx.x * BN_;
    const int wm = (wid >> 2) * 64;     // 2 m-warps x 64
    const int wn = (wid & 3) * 64;      // 4 n-warps x 64

    const int arow = tid >> 3, acg = tid & 7;
    const __nv_bfloat16* Abase = A + (size_t)m0 * KSPLIT_;
    const __nv_bfloat16* Bbase = B + (size_t)n0 * KSPLIT_;

    // ldmatrix lane constants
    const int a_row_l = wm + (lane & 15);
    const uint32_t a_xor = (uint32_t)(a_row_l & 7) << 4;
    const uint32_t a_k2 = (uint32_t)(lane >> 4) * 16;
    const int gq = lane >> 3;
    const int b_row_l = wn + (gq >> 1) * 8 + (lane & 7);
    const uint32_t b_xor = (uint32_t)(b_row_l & 7) << 4;
    const uint32_t b_k2 = (uint32_t)(gq & 1) * 16;

    float acc[4][8][4];
#pragma unroll
    for (int i = 0; i < 4; i++)
#pragma unroll
        for (int j = 0; j < 8; j++)
#pragma unroll
            for (int r = 0; r < 4; r++) acc[i][j][r] = 0.f;

    // A tile rows 0..127 in 4 chunks; B tile rows 0..255 in two groups of 4 chunks
#define LOAD_A_(st_, kc_)                                                           \
    {                                                                               \
        int k0_ = (kc_) * BK_;                                                      \
        _Pragma("unroll")                                                           \
        for (int it_ = 0; it_ < 4; it_++) {                                         \
            int row_ = arow + it_ * 32;                                             \
            uint32_t so_ = (st_) + (uint32_t)row_ * 128 +                           \
                           (((uint32_t)acg * 16) ^ ((uint32_t)(row_ & 7) << 4));    \
            cp_async16(so_, Abase + (size_t)row_ * KSPLIT_ + k0_ + acg * 8);        \
        }                                                                           \
    }
#define LOAD_B_(st_, kc_, half_)                                                    \
    {                                                                               \
        int k0_ = (kc_) * BK_;                                                      \
        _Pragma("unroll")                                                           \
        for (int it_ = 0; it_ < 4; it_++) {                                         \
            int row_ = arow + (it_ + (half_) * 4) * 32;                             \
            uint32_t so_ = (st_) + OFF_B_ + (uint32_t)row_ * 128 +                  \
                           (((uint32_t)acg * 16) ^ ((uint32_t)(row_ & 7) << 4));    \
            cp_async16(so_, Bbase + (size_t)row_ * KSPLIT_ + k0_ + acg * 8);        \
        }                                                                           \
    }

    // prologue: stages 0..2
    LOAD_A_(sb, 0); LOAD_B_(sb, 0, 0); LOAD_B_(sb, 0, 1); CP_COMMIT_();
    LOAD_A_(sb + STAGE_BYTES_, 1); LOAD_B_(sb + STAGE_BYTES_, 1, 0);
    LOAD_B_(sb + STAGE_BYTES_, 1, 1); CP_COMMIT_();
    LOAD_A_(sb + 2 * STAGE_BYTES_, 2); LOAD_B_(sb + 2 * STAGE_BYTES_, 2, 0);
    LOAD_B_(sb + 2 * STAGE_BYTES_, 2, 1); CP_COMMIT_();

    uint32_t Af[2][4][4], Bf[2][8][2];

#define LOAD_FRAGS_(st, ks, buf)                                                    \
    {                                                                               \
        _Pragma("unroll")                                                           \
        for (int mf_ = 0; mf_ < 4; mf_++) {                                         \
            uint32_t ad_ = (st) + (uint32_t)(a_row_l + mf_ * 16) * 128 +            \
                           (((uint32_t)((ks) * 32) + a_k2) ^ a_xor);                \
            ldsm_x4(Af[buf][mf_][0], Af[buf][mf_][1], Af[buf][mf_][2],              \
                    Af[buf][mf_][3], ad_);                                          \
        }                                                                           \
        _Pragma("unroll")                                                           \
        for (int np_ = 0; np_ < 4; np_++) {                                         \
            uint32_t bd_ = (st) + OFF_B_ + (uint32_t)(b_row_l + np_ * 16) * 128 +   \
                           (((uint32_t)((ks) * 32) + b_k2) ^ b_xor);                \
            uint32_t r0_, r1_, r2_, r3_;                                            \
            ldsm_x4(r0_, r1_, r2_, r3_, bd_);                                       \
            Bf[buf][np_ * 2][0] = r0_; Bf[buf][np_ * 2][1] = r1_;                   \
            Bf[buf][np_ * 2 + 1][0] = r2_; Bf[buf][np_ * 2 + 1][1] = r3_;           \
        }                                                                           \
    }

    // wait stage 0, preload its ks0 fragments
    CP_WAIT_(2);
    __syncthreads();
    LOAD_FRAGS_(sb, 0, 0);

    for (int kc = 0; kc < KITERS_; kc++) {
        const uint32_t st = sb + (uint32_t)(kc & 3) * STAGE_BYTES_;
        const int ld = kc + 3;
        const uint32_t lst = sb + (uint32_t)(ld & 3) * STAGE_BYTES_;
        const bool doload = ld < KITERS_;
#pragma unroll
        for (int ks = 0; ks < 4; ks++) {
            if (ks == 0 && doload) { LOAD_A_(lst, ld); }
            if (ks == 1 && doload) { LOAD_B_(lst, ld, 0); }
            if (ks == 2 && doload) { LOAD_B_(lst, ld, 1); }
            if (ks == 2) { CP_COMMIT_(); }
            if (ks == 3) {
                if (kc + 1 < KITERS_) {
                    CP_WAIT_(2);
                    __syncthreads();
                    LOAD_FRAGS_(sb + (uint32_t)((kc + 1) & 3) * STAGE_BYTES_, 0, 0);
                }
            } else {
                LOAD_FRAGS_(st, ks + 1, (ks + 1) & 1);
            }
#pragma unroll
            for (int mf = 0; mf < 4; mf++)
#pragma unroll
                for (int nf = 0; nf < 8; nf++)
                    mma_bf16(acc[mf][nf], Af[ks & 1][mf], Bf[ks & 1][nf]);
        }
    }

    // epilogue: fp32 stores + bias
    const int crow0 = m0 + wm + (lane >> 2);
    const int ccol0 = n0 + wn + (lane & 3) * 2;
#pragma unroll
    for (int mf = 0; mf < 4; mf++) {
#pragma unroll
        for (int nf = 0; nf < 8; nf++) {
            int col = ccol0 + nf * 8;
            float b0 = bias[col], b1 = bias[col + 1];
            int r0 = crow0 + mf * 16;
            float2 v0 = make_float2(acc[mf][nf][0] + b0, acc[mf][nf][1] + b1);
            float2 v1 = make_float2(acc[mf][nf][2] + b0, acc[mf][nf][3] + b1);
            *reinterpret_cast<float2*>(C + (size_t)r0 * ldc + col) = v0;
            *reinterpret_cast<float2*>(C + (size_t)(r0 + 8) * ldc + col) = v1;
        }
    }
#undef LOAD_A_
#undef LOAD_B_
#undef LOAD_FRAGS_
}

// ---------------- kernel 4: 3-tap local attention (warp per token-head) ----------------
__global__ __launch_bounds__(256) void local_attn_kernel() {
    int gw = (blockIdx.x * 256 + threadIdx.x) >> 5;      // KBT_*KH_ warps
    int lid = threadIdx.x & 31;
    int token = gw / KH_;
    int h = gw - token * KH_;
    int t = token & (KT_ - 1);
    size_t base = (size_t)token * KNQKV_ + h * KHD_;     // q at +0, k at +768, v at +1536
    int d0 = lid * 2;

    float q0 = g_qkv[base + d0];
    float q1 = g_qkv[base + d0 + 1];

    float sc[3];
#pragma unroll
    for (int j = 0; j < 3; j++) {
        int off = (j - 1) * KINT_;
        bool valid = ((unsigned)(t + off) < (unsigned)KT_);
        float p = 0.f;
        if (valid) {
            size_t kb = (size_t)((long long)base + (long long)off * KNQKV_) + 768;
            p = q0 * g_qkv[kb + d0] + q1 * g_qkv[kb + d0 + 1];
        }
#pragma unroll
        for (int m = 16; m; m >>= 1) p += __shfl_xor_sync(0xffffffffu, p, m);
        sc[j] = valid ? p * 0.125f : -INFINITY;          // 1/sqrt(64)
    }
    float mx = fmaxf(sc[0], fmaxf(sc[1], sc[2]));
    float e[3], den = 0.f;
#pragma unroll
    for (int j = 0; j < 3; j++) { e[j] = expf(sc[j] - mx); den += e[j]; }
    float rden = 1.f / den;

    float a0 = 0.f, a1 = 0.f;
#pragma unroll
    for (int j = 0; j < 3; j++) {
        int off = (j - 1) * KINT_;
        if ((unsigned)(t + off) < (unsigned)KT_) {
            size_t vb = (size_t)((long long)base + (long long)off * KNQKV_) + 1536;
            float w = e[j] * rden;
            a0 += w * g_qkv[vb + d0];
            a1 += w * g_qkv[vb + d0 + 1];
        }
    }
    __nv_bfloat16 h0 = __float2bfloat16(a0);
    __nv_bfloat16 h1 = __float2bfloat16(a1);
    __nv_bfloat16 l0 = __float2bfloat16(a0 - __bfloat162float(h0));
    __nv_bfloat16 l1 = __float2bfloat16(a1 - __bfloat162float(h1));
    __nv_bfloat162 hh = __halves2bfloat162(h0, h1);
    __nv_bfloat162 ll = __halves2bfloat162(l0, l1);
    size_t base2 = (size_t)token * KSPLIT_ + h * KHD_ + d0;
    *reinterpret_cast<__nv_bfloat162*>(&g_a2[base2])        = hh;
    *reinterpret_cast<__nv_bfloat162*>(&g_a2[base2 + 768])  = ll;
    *reinterpret_cast<__nv_bfloat162*>(&g_a2[base2 + 1536]) = hh;
}

// ---------------- kernel 5: residual + LayerNorm ----------------
__global__ __launch_bounds__(256) void ln_kernel(
    const float* __restrict__ x, const float* __restrict__ gamma,
    const float* __restrict__ beta, float* __restrict__ out) {
    __shared__ float s_sum[8], s_sq[8];
    int r = blockIdx.x, tid = threadIdx.x, wid = tid >> 5, lid = tid & 31;
    size_t base = (size_t)r * KD_;

    float y[3], s = 0.f, s2 = 0.f;
#pragma unroll
    for (int i = 0; i < 3; i++) {
        int c = tid + i * 256;
        float v = g_o[base + c] + x[base + c];
        y[i] = v; s += v; s2 += v * v;
    }
#pragma unroll
    for (int m = 16; m; m >>= 1) {
        s  += __shfl_xor_sync(0xffffffffu, s, m);
        s2 += __shfl_xor_sync(0xffffffffu, s2, m);
    }
    if (lid == 0) { s_sum[wid] = s; s_sq[wid] = s2; }
    __syncthreads();
    float ts = 0.f, ts2 = 0.f;
#pragma unroll
    for (int i = 0; i < 8; i++) { ts += s_sum[i]; ts2 += s_sq[i]; }
    float mean = ts * (1.f / KD_);
    float var  = ts2 * (1.f / KD_) - mean * mean;
    float inv  = rsqrtf(var + 1e-5f);
#pragma unroll
    for (int i = 0; i < 3; i++) {
        int c = tid + i * 256;
        out[base + c] = (y[i] - mean) * inv * gamma[c] + beta[c];
    }
}

// ---------------- launch ----------------
extern "C" void kernel_launch(void* const* d_in, const int* in_sizes, int n_in,
                              void* d_out, int out_size) {
    const float* x     = (const float*)d_in[0];
    const float* Wq    = (const float*)d_in[1];
    const float* bq    = (const float*)d_in[2];
    const float* Wk    = (const float*)d_in[3];
    const float* bk    = (const float*)d_in[4];
    const float* Wv    = (const float*)d_in[5];
    const float* bv    = (const float*)d_in[6];
    const float* Wo    = (const float*)d_in[7];
    const float* bo    = (const float*)d_in[8];
    const float* gamma = (const float*)d_in[9];
    const float* beta  = (const float*)d_in[10];

    void *p_a2, *p_w2, *p_qkv, *p_o, *p_bqkv;
    cudaGetSymbolAddress(&p_a2,  g_a2);
    cudaGetSymbolAddress(&p_w2,  g_w2);
    cudaGetSymbolAddress(&p_qkv, g_qkv);
    cudaGetSymbolAddress(&p_o,   g_o);
    cudaGetSymbolAddress(&p_bqkv, g_bqkv);

    const __nv_bfloat16* a2 = (const __nv_bfloat16*)p_a2;
    const __nv_bfloat16* w2 = (const __nv_bfloat16*)p_w2;
    const size_t WSTRIDE = (size_t)KD_ * KSPLIT_;

    cudaFuncSetAttribute(gemm_kernel,
                         cudaFuncAttributeMaxDynamicSharedMemorySize, (int)SMEM_BYTES_);

    prep_weights_kernel<<<WELEM_ / 256, 256>>>(Wq, Wk, Wv, Wo, bq, bk, bv);
    split_x_kernel<<<(int)(KNELEM_ / 4 / 256), 256>>>(x);

    // fused QKV: C[32768, 2304]
    dim3 gqkv(KNQKV_ / BN_, KBT_ / BM_);   // (9, 256)
    gemm_kernel<<<gqkv, 256, SMEM_BYTES_>>>(a2, w2, (const float*)p_bqkv,
                                            (float*)p_qkv, KNQKV_);
    local_attn_kernel<<<KBT_ * KH_ / 8, 256>>>();
    // O projection: C[32768, 768]
    dim3 go(KD_ / BN_, KBT_ / BM_);        // (3, 256)
    gemm_kernel<<<go, 256, SMEM_BYTES_>>>(a2, w2 + 3 * WSTRIDE, bo, (float*)p_o, KD_);
    ln_kernel<<<KBT_, 256>>>(x, gamma, beta, (float*)d_out);
}

// round 9
// speedup vs baseline: 1.2817x; 1.0885x over previous
#include <cuda_runtime.h>
#include <cuda_bf16.h>
#include <cstdint>
#include <math.h>

// ---------------- problem constants ----------------
#define KB_   8
#define KT_   4096
#define KD_   768
#define KH_   12
#define KHD_  64
#define KINT_ 3
#define KBT_  (KB_ * KT_)                 // 32768
#define KNELEM_ ((size_t)KBT_ * KD_)      // 25165824
#define KSPLIT_ 2304                      // 3 * 768 (hi | lo | hi concat along K)
#define KNQKV_ 2304                       // Wq|Wk|Wv stacked along N
#define WELEM_ (KD_ * KD_)

// GEMM tiling: 128x128 CTA, 64x32 warp, 3 stages -> 2 CTAs/SM
#define BM_ 128
#define BN_ 128
#define BK_ 64
#define KITERS_ (KSPLIT_ / BK_)           // 36
#define STAGES_ 3
#define STAGE_BYTES_ 32768u               // A 16KB + B 16KB
#define OFF_B_ 16384u
#define SMEM_BYTES_ (STAGES_ * STAGE_BYTES_)   // 98304

// ---------------- device scratch ----------------
__device__ __nv_bfloat16 g_a2[(size_t)KBT_ * KSPLIT_];       // split activations
__device__ __nv_bfloat16 g_w2[4 * (size_t)KD_ * KSPLIT_];    // split transposed weights (q,k,v,o)
__device__ float g_bqkv[KNQKV_];                             // concat bias q|k|v
__device__ float g_qkv[(size_t)KBT_ * KNQKV_];               // fused QKV output
__device__ float g_o[KNELEM_];

// ---------------- helpers ----------------
__device__ __forceinline__ uint32_t smem_u32(const void* p) {
    return (uint32_t)__cvta_generic_to_shared(p);
}

__device__ __forceinline__ void cp_async16(uint32_t saddr, const void* gaddr) {
    asm volatile("cp.async.cg.shared.global [%0], [%1], 16;" :: "r"(saddr), "l"(gaddr));
}
#define CP_COMMIT_()  asm volatile("cp.async.commit_group;" ::: "memory")
#define CP_WAIT_(n)   asm volatile("cp.async.wait_group %0;" :: "n"(n) : "memory")

__device__ __forceinline__ void ldsm_x4(uint32_t& r0, uint32_t& r1, uint32_t& r2, uint32_t& r3,
                                        uint32_t addr) {
    asm volatile("ldmatrix.sync.aligned.m8n8.x4.shared.b16 {%0,%1,%2,%3}, [%4];"
                 : "=r"(r0), "=r"(r1), "=r"(r2), "=r"(r3) : "r"(addr));
}

__device__ __forceinline__ void mma_bf16(float* c, const uint32_t* a, const uint32_t* b) {
    asm volatile(
        "mma.sync.aligned.m16n8k16.row.col.f32.bf16.bf16.f32 "
        "{%0,%1,%2,%3}, {%4,%5,%6,%7}, {%8,%9}, {%0,%1,%2,%3};"
        : "+f"(c[0]), "+f"(c[1]), "+f"(c[2]), "+f"(c[3])
        : "r"(a[0]), "r"(a[1]), "r"(a[2]), "r"(a[3]), "r"(b[0]), "r"(b[1]));
}

// ---------------- kernel 1: transpose + split weights, concat bias ----------------
__global__ __launch_bounds__(256) void prep_weights_kernel(
    const float* __restrict__ Wq, const float* __restrict__ Wk,
    const float* __restrict__ Wv, const float* __restrict__ Wo,
    const float* __restrict__ bq, const float* __restrict__ bk,
    const float* __restrict__ bv) {
    int idx = blockIdx.x * 256 + threadIdx.x;       // over D*D
    int n = idx / KD_;
    int k = idx - n * KD_;
    const float* Ws[4] = {Wq, Wk, Wv, Wo};
#pragma unroll
    for (int w = 0; w < 4; w++) {
        float val = Ws[w][(size_t)k * KD_ + n];     // W[k][n] -> B[n][k]
        __nv_bfloat16 hi = __float2bfloat16(val);
        __nv_bfloat16 lo = __float2bfloat16(val - __bfloat162float(hi));
        size_t base = (size_t)w * KD_ * KSPLIT_ + (size_t)n * KSPLIT_;
        g_w2[base + k]        = hi;
        g_w2[base + 768 + k]  = hi;
        g_w2[base + 1536 + k] = lo;
    }
    if (idx < KNQKV_) {
        g_bqkv[idx] = (idx < 768) ? bq[idx] : (idx < 1536) ? bk[idx - 768] : bv[idx - 1536];
    }
}

// ---------------- kernel 2: split x -> [hi | lo | hi] rows of 2304 (float4) ----------------
__global__ __launch_bounds__(256) void split_x_kernel(const float* __restrict__ x) {
    long long gid = (long long)blockIdx.x * 256 + threadIdx.x;   // over KNELEM/4
    long long i = gid * 4;
    int row = (int)(i / KD_);
    int col = (int)(i - (long long)row * KD_);
    float4 v = *reinterpret_cast<const float4*>(x + i);
    __nv_bfloat16 h0 = __float2bfloat16(v.x), h1 = __float2bfloat16(v.y);
    __nv_bfloat16 h2 = __float2bfloat16(v.z), h3 = __float2bfloat16(v.w);
    __nv_bfloat16 l0 = __float2bfloat16(v.x - __bfloat162float(h0));
    __nv_bfloat16 l1 = __float2bfloat16(v.y - __bfloat162float(h1));
    __nv_bfloat16 l2 = __float2bfloat16(v.z - __bfloat162float(h2));
    __nv_bfloat16 l3 = __float2bfloat16(v.w - __bfloat162float(h3));
    uint2 hh, ll;
    hh.x = ((uint32_t)__bfloat16_as_ushort(h1) << 16) | __bfloat16_as_ushort(h0);
    hh.y = ((uint32_t)__bfloat16_as_ushort(h3) << 16) | __bfloat16_as_ushort(h2);
    ll.x = ((uint32_t)__bfloat16_as_ushort(l1) << 16) | __bfloat16_as_ushort(l0);
    ll.y = ((uint32_t)__bfloat16_as_ushort(l3) << 16) | __bfloat16_as_ushort(l2);
    size_t base = (size_t)row * KSPLIT_ + col;
    *reinterpret_cast<uint2*>(&g_a2[base])        = hh;
    *reinterpret_cast<uint2*>(&g_a2[base + 768])  = ll;
    *reinterpret_cast<uint2*>(&g_a2[base + 1536]) = hh;
}

// ---------------- kernel 3: pipelined bf16 mma.sync GEMM (128x128 CTA, 64x32 warp, 2 CTA/SM) ----------------
// C[M, ldc] = A'[M,2304] * B'[ldc,2304]^T + bias
__global__ __launch_bounds__(256, 2) void gemm_kernel(
    const __nv_bfloat16* __restrict__ A, const __nv_bfloat16* __restrict__ B,
    const float* __restrict__ bias, float* __restrict__ C, int ldc) {
    extern __shared__ char smem[];
    const uint32_t sb = smem_u32(smem);
    const int tid = threadIdx.x, lane = tid & 31, wid = tid >> 5;
    const int m0 = blockIdx.y * BM_;
    const int n0 = blockIdx.x * BN_;
    const int wm = (wid >> 2) * 64;     // 2 m-warps x 64
    const int wn = (wid & 3) * 32;      // 4 n-warps x 32

    const int arow = tid >> 3, acg = tid & 7;
    const __nv_bfloat16* Abase = A + (size_t)m0 * KSPLIT_;
    const __nv_bfloat16* Bbase = B + (size_t)n0 * KSPLIT_;

    // ldmatrix lane constants
    const int a_row_l = wm + (lane & 15);
    const uint32_t a_xor = (uint32_t)(a_row_l & 7) << 4;
    const uint32_t a_k2 = (uint32_t)(lane >> 4) * 16;
    const int gq = lane >> 3;
    const int b_row_l = wn + (gq >> 1) * 8 + (lane & 7);
    const uint32_t b_xor = (uint32_t)(b_row_l & 7) << 4;
    const uint32_t b_k2 = (uint32_t)(gq & 1) * 16;

    float acc[4][4][4];
#pragma unroll
    for (int i = 0; i < 4; i++)
#pragma unroll
        for (int j = 0; j < 4; j++)
#pragma unroll
            for (int r = 0; r < 4; r++) acc[i][j][r] = 0.f;

#define LOAD_A_(st_, kc_)                                                           \
    {                                                                               \
        int k0_ = (kc_) * BK_;                                                      \
        _Pragma("unroll")                                                           \
        for (int it_ = 0; it_ < 4; it_++) {                                         \
            int row_ = arow + it_ * 32;                                             \
            uint32_t so_ = (st_) + (uint32_t)row_ * 128 +                           \
                           (((uint32_t)acg * 16) ^ ((uint32_t)(row_ & 7) << 4));    \
            cp_async16(so_, Abase + (size_t)row_ * KSPLIT_ + k0_ + acg * 8);        \
        }                                                                           \
    }
#define LOAD_B_(st_, kc_)                                                           \
    {                                                                               \
        int k0_ = (kc_) * BK_;                                                      \
        _Pragma("unroll")                                                           \
        for (int it_ = 0; it_ < 4; it_++) {                                         \
            int row_ = arow + it_ * 32;                                             \
            uint32_t so_ = (st_) + OFF_B_ + (uint32_t)row_ * 128 +                  \
                           (((uint32_t)acg * 16) ^ ((uint32_t)(row_ & 7) << 4));    \
            cp_async16(so_, Bbase + (size_t)row_ * KSPLIT_ + k0_ + acg * 8);        \
        }                                                                           \
    }

    // prologue: stages 0..1
    LOAD_A_(sb, 0); LOAD_B_(sb, 0); CP_COMMIT_();
    LOAD_A_(sb + STAGE_BYTES_, 1); LOAD_B_(sb + STAGE_BYTES_, 1); CP_COMMIT_();

    uint32_t Af[2][4][4], Bf[2][4][2];

#define LOAD_FRAGS_(st, ks, buf)                                                    \
    {                                                                               \
        _Pragma("unroll")                                                           \
        for (int mf_ = 0; mf_ < 4; mf_++) {                                         \
            uint32_t ad_ = (st) + (uint32_t)(a_row_l + mf_ * 16) * 128 +            \
                           (((uint32_t)((ks) * 32) + a_k2) ^ a_xor);                \
            ldsm_x4(Af[buf][mf_][0], Af[buf][mf_][1], Af[buf][mf_][2],              \
                    Af[buf][mf_][3], ad_);                                          \
        }                                                                           \
        _Pragma("unroll")                                                           \
        for (int np_ = 0; np_ < 2; np_++) {                                         \
            uint32_t bd_ = (st) + OFF_B_ + (uint32_t)(b_row_l + np_ * 16) * 128 +   \
                           (((uint32_t)((ks) * 32) + b_k2) ^ b_xor);                \
            uint32_t r0_, r1_, r2_, r3_;                                            \
            ldsm_x4(r0_, r1_, r2_, r3_, bd_);                                       \
            Bf[buf][np_ * 2][0] = r0_; Bf[buf][np_ * 2][1] = r1_;                   \
            Bf[buf][np_ * 2 + 1][0] = r2_; Bf[buf][np_ * 2 + 1][1] = r3_;           \
        }                                                                           \
    }

    // wait stage 0, preload its ks0 fragments
    CP_WAIT_(1);
    __syncthreads();
    LOAD_FRAGS_(sb, 0, 0);

    uint32_t stage_off[3] = {0u, STAGE_BYTES_, 2u * STAGE_BYTES_};
    int cur = 0;                 // stage index of kc
    for (int kc = 0; kc < KITERS_; kc++) {
        const uint32_t st = sb + stage_off[cur];
        int ldstage = cur + 2; if (ldstage >= 3) ldstage -= 3;
        const uint32_t lst = sb + stage_off[ldstage];
        int nxt = cur + 1; if (nxt >= 3) nxt -= 3;
        const int ld = kc + 2;
        const bool doload = ld < KITERS_;
#pragma unroll
        for (int ks = 0; ks < 4; ks++) {
            if (ks == 0 && doload) { LOAD_A_(lst, ld); }
            if (ks == 1 && doload) { LOAD_B_(lst, ld); }
            if (ks == 1) { CP_COMMIT_(); }
            if (ks == 3) {
                if (kc + 1 < KITERS_) {
                    CP_WAIT_(1);
                    __syncthreads();
                    LOAD_FRAGS_(sb + stage_off[nxt], 0, 0);
                }
            } else {
                LOAD_FRAGS_(st, ks + 1, (ks + 1) & 1);
            }
#pragma unroll
            for (int mf = 0; mf < 4; mf++)
#pragma unroll
                for (int nf = 0; nf < 4; nf++)
                    mma_bf16(acc[mf][nf], Af[ks & 1][mf], Bf[ks & 1][nf]);
        }
        cur = nxt;
    }

    // epilogue: fp32 stores + bias
    const int crow0 = m0 + wm + (lane >> 2);
    const int ccol0 = n0 + wn + (lane & 3) * 2;
#pragma unroll
    for (int mf = 0; mf < 4; mf++) {
#pragma unroll
        for (int nf = 0; nf < 4; nf++) {
            int col = ccol0 + nf * 8;
            float b0 = bias[col], b1 = bias[col + 1];
            int r0 = crow0 + mf * 16;
            float2 v0 = make_float2(acc[mf][nf][0] + b0, acc[mf][nf][1] + b1);
            float2 v1 = make_float2(acc[mf][nf][2] + b0, acc[mf][nf][3] + b1);
            *reinterpret_cast<float2*>(C + (size_t)r0 * ldc + col) = v0;
            *reinterpret_cast<float2*>(C + (size_t)(r0 + 8) * ldc + col) = v1;
        }
    }
#undef LOAD_A_
#undef LOAD_B_
#undef LOAD_FRAGS_
}

// ---------------- kernel 4: 3-tap local attention (warp per token x head-pair) ----------------
// lane covers 4 consecutive dims; lanes 0-15 -> head 2*hp, lanes 16-31 -> head 2*hp+1.
__global__ __launch_bounds__(256) void local_attn_kernel() {
    int gw = (blockIdx.x * 256 + threadIdx.x) >> 5;      // KBT_*6 warps
    int lid = threadIdx.x & 31;
    int token = gw / 6;
    int hp = gw - token * 6;
    int t = token & (KT_ - 1);
    size_t base = (size_t)token * KNQKV_ + hp * 128 + lid * 4;  // q at +0, k +768, v +1536

    float4 q = *reinterpret_cast<const float4*>(&g_qkv[base]);

    float sc[3];
#pragma unroll
    for (int j = 0; j < 3; j++) {
        int off = (j - 1) * KINT_;
        bool valid = ((unsigned)(t + off) < (unsigned)KT_);
        float p = 0.f;
        if (valid) {
            const float4 k = *reinterpret_cast<const float4*>(
                &g_qkv[base + (long long)off * KNQKV_ + 768]);
            p = q.x * k.x + q.y * k.y + q.z * k.z + q.w * k.w;
        }
#pragma unroll
        for (int m = 8; m; m >>= 1) p += __shfl_xor_sync(0xffffffffu, p, m);
        sc[j] = valid ? p * 0.125f : -INFINITY;          // 1/sqrt(64)
    }
    float mx = fmaxf(sc[0], fmaxf(sc[1], sc[2]));
    float e[3], den = 0.f;
#pragma unroll
    for (int j = 0; j < 3; j++) { e[j] = __expf(sc[j] - mx); den += e[j]; }
    float rden = 1.f / den;

    float a0 = 0.f, a1 = 0.f, a2 = 0.f, a3 = 0.f;
#pragma unroll
    for (int j = 0; j < 3; j++) {
        int off = (j - 1) * KINT_;
        if ((unsigned)(t + off) < (unsigned)KT_) {
            const float4 v = *reinterpret_cast<const float4*>(
                &g_qkv[base + (long long)off * KNQKV_ + 1536]);
            float w = e[j] * rden;
            a0 += w * v.x; a1 += w * v.y; a2 += w * v.z; a3 += w * v.w;
        }
    }
    __nv_bfloat16 h0 = __float2bfloat16(a0), h1 = __float2bfloat16(a1);
    __nv_bfloat16 h2 = __float2bfloat16(a2), h3 = __float2bfloat16(a3);
    __nv_bfloat16 l0 = __float2bfloat16(a0 - __bfloat162float(h0));
    __nv_bfloat16 l1 = __float2bfloat16(a1 - __bfloat162float(h1));
    __nv_bfloat16 l2 = __float2bfloat16(a2 - __bfloat162float(h2));
    __nv_bfloat16 l3 = __float2bfloat16(a3 - __bfloat162float(h3));
    uint2 hh, ll;
    hh.x = ((uint32_t)__bfloat16_as_ushort(h1) << 16) | __bfloat16_as_ushort(h0);
    hh.y = ((uint32_t)__bfloat16_as_ushort(h3) << 16) | __bfloat16_as_ushort(h2);
    ll.x = ((uint32_t)__bfloat16_as_ushort(l1) << 16) | __bfloat16_as_ushort(l0);
    ll.y = ((uint32_t)__bfloat16_as_ushort(l3) << 16) | __bfloat16_as_ushort(l2);
    size_t base2 = (size_t)token * KSPLIT_ + hp * 128 + lid * 4;
    *reinterpret_cast<uint2*>(&g_a2[base2])        = hh;
    *reinterpret_cast<uint2*>(&g_a2[base2 + 768])  = ll;
    *reinterpret_cast<uint2*>(&g_a2[base2 + 1536]) = hh;
}

// ---------------- kernel 5: residual + LayerNorm ----------------
__global__ __launch_bounds__(256) void ln_kernel(
    const float* __restrict__ x, const float* __restrict__ gamma,
    const float* __restrict__ beta, float* __restrict__ out) {
    __shared__ float s_sum[8], s_sq[8];
    int r = blockIdx.x, tid = threadIdx.x, wid = tid >> 5, lid = tid & 31;
    size_t base = (size_t)r * KD_;

    float y[3], s = 0.f, s2 = 0.f;
#pragma unroll
    for (int i = 0; i < 3; i++) {
        int c = tid + i * 256;
        float v = g_o[base + c] + x[base + c];
        y[i] = v; s += v; s2 += v * v;
    }
#pragma unroll
    for (int m = 16; m; m >>= 1) {
        s  += __shfl_xor_sync(0xffffffffu, s, m);
        s2 += __shfl_xor_sync(0xffffffffu, s2, m);
    }
    if (lid == 0) { s_sum[wid] = s; s_sq[wid] = s2; }
    __syncthreads();
    float ts = 0.f, ts2 = 0.f;
#pragma unroll
    for (int i = 0; i < 8; i++) { ts += s_sum[i]; ts2 += s_sq[i]; }
    float mean = ts * (1.f / KD_);
    float var  = ts2 * (1.f / KD_) - mean * mean;
    float inv  = rsqrtf(var + 1e-5f);
#pragma unroll
    for (int i = 0; i < 3; i++) {
        int c = tid + i * 256;
        out[base + c] = (y[i] - mean) * inv * gamma[c] + beta[c];
    }
}

// ---------------- launch ----------------
extern "C" void kernel_launch(void* const* d_in, const int* in_sizes, int n_in,
                              void* d_out, int out_size) {
    const float* x     = (const float*)d_in[0];
    const float* Wq    = (const float*)d_in[1];
    const float* bq    = (const float*)d_in[2];
    const float* Wk    = (const float*)d_in[3];
    const float* bk    = (const float*)d_in[4];
    const float* Wv    = (const float*)d_in[5];
    const float* bv    = (const float*)d_in[6];
    const float* Wo    = (const float*)d_in[7];
    const float* bo    = (const float*)d_in[8];
    const float* gamma = (const float*)d_in[9];
    const float* beta  = (const float*)d_in[10];

    void *p_a2, *p_w2, *p_qkv, *p_o, *p_bqkv;
    cudaGetSymbolAddress(&p_a2,  g_a2);
    cudaGetSymbolAddress(&p_w2,  g_w2);
    cudaGetSymbolAddress(&p_qkv, g_qkv);
    cudaGetSymbolAddress(&p_o,   g_o);
    cudaGetSymbolAddress(&p_bqkv, g_bqkv);

    const __nv_bfloat16* a2 = (const __nv_bfloat16*)p_a2;
    const __nv_bfloat16* w2 = (const __nv_bfloat16*)p_w2;
    const size_t WSTRIDE = (size_t)KD_ * KSPLIT_;

    cudaFuncSetAttribute(gemm_kernel,
                         cudaFuncAttributeMaxDynamicSharedMemorySize, (int)SMEM_BYTES_);

    prep_weights_kernel<<<WELEM_ / 256, 256>>>(Wq, Wk, Wv, Wo, bq, bk, bv);
    split_x_kernel<<<(int)(KNELEM_ / 4 / 256), 256>>>(x);

    // fused QKV: C[32768, 2304]
    dim3 gqkv(KNQKV_ / BN_, KBT_ / BM_);   // (18, 256)
    gemm_kernel<<<gqkv, 256, SMEM_BYTES_>>>(a2, w2, (const float*)p_bqkv,
                                            (float*)p_qkv, KNQKV_);
    // attention: 32768 tokens * 6 head-pairs = 196608 warps = 24576 blocks
    local_attn_kernel<<<KBT_ * 6 / 8, 256>>>();
    // O projection: C[32768, 768]
    dim3 go(KD_ / BN_, KBT_ / BM_);        // (6, 256)
    gemm_kernel<<<go, 256, SMEM_BYTES_>>>(a2, w2 + 3 * WSTRIDE, bo, (float*)p_o, KD_);
    ln_kernel<<<KBT_, 256>>>(x, gamma, beta, (float*)d_out);
}